// round 5
// baseline (speedup 1.0000x reference)
#include <cuda_runtime.h>
#include <math.h>
#include <stdint.h>

#define NE 16
#define NS 64
#define NDM 128
#define NP 2048
#define NB 8
#define NC 256
#define NW 3
#define NV 5

// ---------------- global scratch (no allocs allowed) ----------------
__device__ int           g_routes[NE][NW];
__device__ float         g_wdir[NV];
__device__ float         g_aw[NE];
__device__ float         g_invT;
__device__ float         g_qd[NE][NS][NV];
__device__ float         g_kd[NE][NS][NV];
__device__ int           g_idx[NE][NC];
__device__ unsigned char g_valid[NE][NC];
__device__ int           g_cnt[NE];
__device__ float         g_qaff[NE][NV][NB][NC];
__device__ float         g_kaff[NE][NV][NB][NC];
__device__ float         g_kmin[NE][NV][NB];
__device__ float         g_kmax[NE][NV][NB];
__device__ float         g_vbuf[NE][NB][NC][NDM];   // 16.8 MB, fits L2

// ---------------- K0: setup (routes, wdir, aw, dirs, qd/kd) ----------------
__global__ __launch_bounds__(256) void k_setup(
    const float* __restrict__ alpha, const float* __restrict__ penta,
    const float* __restrict__ fusion_w, const float* __restrict__ q_w,
    const float* __restrict__ k_w, const float* __restrict__ temp)
{
    int e = blockIdx.x, t = threadIdx.x;
    __shared__ float dirs[NV][NDM];
    __shared__ float rn[NV];
    int w = t >> 5, lane = t & 31;
    if (w < NV) {
        float s = 0.f;
        for (int d = lane; d < NDM; d += 32) {
            float x = penta[(e * NV + w) * NDM + d];
            s += x * x;
        }
        for (int off = 16; off; off >>= 1) s += __shfl_xor_sync(0xffffffffu, s, off);
        if (lane == 0) rn[w] = rsqrtf(s);
    }
    __syncthreads();
    for (int i = t; i < NV * NDM; i += 256) {
        int v = i >> 7, d = i & 127;
        dirs[v][d] = penta[(e * NV + v) * NDM + d] * rn[v];
    }
    __syncthreads();
    for (int i = t; i < NS * NV; i += 256) {
        int s = i / NV, v = i % NV;
        float aq = 0.f, ak = 0.f;
        for (int d = 0; d < NDM; d++) {
            float dd = dirs[v][d];
            aq += q_w[(e * NS + s) * NDM + d] * dd;
            ak += k_w[(e * NS + s) * NDM + d] * dd;
        }
        g_qd[e][s][v] = aq;
        g_kd[e][s][v] = ak;
    }
    if (e == 0) {
        if (t < NE) g_aw[t] = 1.f / (1.f + expf(-alpha[t]));
        if (t == 0) {
            g_invT = 1.0f / temp[0];
            // softmax over fusion_w
            float mx = -1e30f;
            for (int i = 0; i < NV; i++) mx = fmaxf(mx, fusion_w[i]);
            float ex[NV], sm = 0.f;
            for (int i = 0; i < NV; i++) { ex[i] = expf(fusion_w[i] - mx); sm += ex[i]; }
            for (int i = 0; i < NV; i++) g_wdir[i] = ex[i] / sm;
            // cantor coords in double to match python, cast to f32
            float coords[NE];
            for (int i = 0; i < NE; i++) {
                double x = (double)i / 15.0;
                x = fmax(1e-6, fmin(x, 1.0 - 1e-6));
                double val = 0.0, fac = 0.5;
                for (int k = 0; k < 8; k++) {
                    x *= 3.0;
                    int d = (int)x;
                    x -= (double)d;
                    if (d == 2) val += fac;
                    fac *= 0.5;
                }
                coords[i] = (float)val;
            }
            for (int ee = 0; ee < NE; ee++) {
                float key[NE]; int ord[NE];
                for (int i = 0; i < NE; i++) { key[i] = fabsf(coords[i] - coords[ee]); ord[i] = i; }
                // stable insertion sort (strict >) ascending
                for (int i = 1; i < NE; i++) {
                    float kv = key[i]; int ov = ord[i]; int j = i - 1;
                    while (j >= 0 && key[j] > kv) { key[j + 1] = key[j]; ord[j + 1] = ord[j]; j--; }
                    key[j + 1] = kv; ord[j + 1] = ov;
                }
                for (int wv = 0; wv < NW; wv++) g_routes[ee][wv] = ord[wv];
            }
        }
    }
}

// ---------------- K1: dispatch ----------------
__global__ __launch_bounds__(256) void k_dispatch(const float* __restrict__ fp)
{
    __shared__ float sf[NP];
    int e = blockIdx.x, t = threadIdx.x;
    for (int i = t; i < NP; i += 256) sf[i] = fp[i];
    __syncthreads();
    if (t == 0) {
        float lo = (float)e / 16.0f, hi = (float)(e + 1) / 16.0f;
        int cnt = 0;
        for (int i = 0; i < NP && cnt < NC; i++) {
            float f = sf[i];
            bool m = (f >= lo) && ((e == NE - 1) ? (f <= hi) : (f < hi));
            if (m) { g_idx[e][cnt] = i; g_valid[e][cnt] = 1; cnt++; }
        }
        g_cnt[e] = cnt;
        for (int i = 0; i < NP && cnt < NC; i++) {
            float f = sf[i];
            bool m = (f >= lo) && ((e == NE - 1) ? (f <= hi) : (f < hi));
            if (!m) { g_idx[e][cnt] = i; g_valid[e][cnt] = 0; cnt++; }
        }
    }
}

// ---------------- K zero output ----------------
__global__ __launch_bounds__(256) void k_zero(float* __restrict__ out, int n4)
{
    int i = blockIdx.x * blockDim.x + threadIdx.x;
    if (i < n4) reinterpret_cast<float4*>(out)[i] = make_float4(0.f, 0.f, 0.f, 0.f);
}

// ---------------- K2: gather + gate + affinities + V projection ----------------
struct __align__(16) Smem2 {
    float vw[NS][132];       // padded, rows 16B aligned
    float feats[NC][65];     // padded +1, conflict-free for [tid][s]
    float qd[NS][NV];
    float kd[NS][NV];
    float w1[NS][16];
    float b1[16];
    float w2[16];
    float b2;
    float red[64];
    int   idxs[NC];
    unsigned char vld[NC];
};

__global__ __launch_bounds__(256) void k_featproc(
    const float* __restrict__ tokens, const float* __restrict__ gw1,
    const float* __restrict__ gb1, const float* __restrict__ gw2,
    const float* __restrict__ gb2, const float* __restrict__ vwg)
{
    extern __shared__ char smraw[];
    Smem2& Sm = *reinterpret_cast<Smem2*>(smraw);
    int e = blockIdx.x, b = blockIdx.y, t = threadIdx.x;

    Sm.idxs[t] = g_idx[e][t];
    Sm.vld[t]  = g_valid[e][t];
    for (int i = t; i < NS * 16; i += 256) Sm.w1[i / 16][i % 16] = gw1[e * NS * 16 + i];
    if (t < 16) Sm.b1[t] = gb1[e * 16 + t];
    if (t < 16) Sm.w2[t] = gw2[e * 16 + t];
    if (t == 0) Sm.b2 = gb2[e];
    for (int i = t; i < NS * NV; i += 256) {
        Sm.qd[i / NV][i % NV] = g_qd[e][i / NV][i % NV];
        Sm.kd[i / NV][i % NV] = g_kd[e][i / NV][i % NV];
    }
    for (int i = t; i < NS * NDM; i += 256) Sm.vw[i / NDM][i % NDM] = vwg[e * NS * NDM + i];
    __syncthreads();

    // gather feats: warp per row, float2 per lane
    {
        int w = t >> 5, lane = t & 31;
        for (int r = w; r < NC; r += 8) {
            int pos = Sm.idxs[r];
            const float* src = tokens + ((size_t)b * NP + pos) * 1024 + e * NS;
            float2 v2 = reinterpret_cast<const float2*>(src)[lane];
            Sm.feats[r][lane * 2]     = v2.x;
            Sm.feats[r][lane * 2 + 1] = v2.y;
        }
    }
    __syncthreads();

    // gate + scale + affinities : thread t owns row t
    float aw = g_aw[e];
    {
        int i = t;
        float h[16];
#pragma unroll
        for (int hh = 0; hh < 16; hh++) h[hh] = Sm.b1[hh];
        for (int s = 0; s < NS; s++) {
            float f = Sm.feats[i][s];
#pragma unroll
            for (int hh = 0; hh < 16; hh++) h[hh] += f * Sm.w1[s][hh];
        }
        float o = Sm.b2;
#pragma unroll
        for (int hh = 0; hh < 16; hh++) {
            float x = h[hh];
            float g = 0.5f * x * (1.0f + tanhf(0.7978845608028654f * (x + 0.044715f * x * x * x)));
            o += g * Sm.w2[hh];
        }
        float gsig  = 1.f / (1.f + expf(-o));
        float scale = gsig * aw + (1.f - aw);

        float qa[NV], ka[NV];
#pragma unroll
        for (int v = 0; v < NV; v++) { qa[v] = 0.f; ka[v] = 0.f; }
        for (int s = 0; s < NS; s++) {
            float f = Sm.feats[i][s] * scale;
            Sm.feats[i][s] = f;
#pragma unroll
            for (int v = 0; v < NV; v++) {
                qa[v] += f * Sm.qd[s][v];
                ka[v] += f * Sm.kd[s][v];
            }
        }
        bool vl = (Sm.vld[i] != 0);
#pragma unroll
        for (int v = 0; v < NV; v++) {
            g_qaff[e][v][b][i] = qa[v];
            g_kaff[e][v][b][i] = ka[v];
        }
        // per (e,v,b) min/max of valid kaff
        int w = t >> 5, lane = t & 31;
        for (int v = 0; v < NV; v++) {
            float kmx = vl ? ka[v] : -INFINITY;
            float kmn = vl ? ka[v] :  INFINITY;
            for (int off = 16; off; off >>= 1) {
                kmx = fmaxf(kmx, __shfl_xor_sync(0xffffffffu, kmx, off));
                kmn = fminf(kmn, __shfl_xor_sync(0xffffffffu, kmn, off));
            }
            if (lane == 0) { Sm.red[w] = kmx; Sm.red[8 + w] = kmn; }
            __syncthreads();
            if (t == 0) {
                float mx = -INFINITY, mn = INFINITY;
                for (int ww = 0; ww < 8; ww++) {
                    mx = fmaxf(mx, Sm.red[ww]);
                    mn = fminf(mn, Sm.red[8 + ww]);
                }
                g_kmax[e][v][b] = mx;
                g_kmin[e][v][b] = mn;
            }
            __syncthreads();
        }
    }
    __syncthreads();

    // V = feats(256x64) @ vw(64x128), 4 sub-tiles of 64 rows, 16x16 threads x (4x8)
    int tx = t & 15, ty = t >> 4;
    for (int sub = 0; sub < 4; sub++) {
        int i0 = sub * 64 + ty * 4;
        float acc[4][8];
#pragma unroll
        for (int r = 0; r < 4; r++)
#pragma unroll
            for (int c = 0; c < 8; c++) acc[r][c] = 0.f;
#pragma unroll 8
        for (int k = 0; k < NS; k++) {
            float a0 = Sm.feats[i0 + 0][k];
            float a1 = Sm.feats[i0 + 1][k];
            float a2 = Sm.feats[i0 + 2][k];
            float a3 = Sm.feats[i0 + 3][k];
            float4 b0 = *reinterpret_cast<const float4*>(&Sm.vw[k][tx * 8]);
            float4 b1 = *reinterpret_cast<const float4*>(&Sm.vw[k][tx * 8 + 4]);
            float bv[8] = {b0.x, b0.y, b0.z, b0.w, b1.x, b1.y, b1.z, b1.w};
            float av[4] = {a0, a1, a2, a3};
#pragma unroll
            for (int r = 0; r < 4; r++)
#pragma unroll
                for (int c = 0; c < 8; c++) acc[r][c] += av[r] * bv[c];
        }
#pragma unroll
        for (int r = 0; r < 4; r++) {
            float* dst = &g_vbuf[e][b][i0 + r][tx * 8];
            reinterpret_cast<float4*>(dst)[0] = make_float4(acc[r][0], acc[r][1], acc[r][2], acc[r][3]);
            reinterpret_cast<float4*>(dst)[1] = make_float4(acc[r][4], acc[r][5], acc[r][6], acc[r][7]);
        }
    }
}

// ---------------- K3: fused multi-direction attention ----------------
struct __align__(16) Smem3 {
    float vchunk[64][132];   // 33792 B
    float wsub[64][68];      // 17408 B (combined weights, [j][i])
    float kall[NV][NW * NC]; // 15360 B
    float qvI[NV][64];       // q * invT
    float miv[NV][64];
    float cw[NV][64];        // wdir[v]/Z_iv
    float zp[64][4];
    float kmaxc[NV];
    float kminc[NV];
    int   idxs[64];
    int   cnt3[NW];
    unsigned char vj[NW * NC];
    unsigned char vld[64];
};

__global__ __launch_bounds__(256) void k_attn(float* __restrict__ out)
{
    int e = blockIdx.x, b = blockIdx.y, it = blockIdx.z, t = threadIdx.x;
    int i0 = it * 64;
    if (i0 >= g_cnt[e]) return;   // whole row-tile invalid -> nothing to write

    extern __shared__ char smraw[];
    Smem3& Sm = *reinterpret_cast<Smem3*>(smraw);

    int nb0 = g_routes[e][0], nb1 = g_routes[e][1], nb2 = g_routes[e][2];
    int nbs[NW] = {nb0, nb1, nb2};
    float invT = g_invT;

    if (t < NW) Sm.cnt3[t] = g_cnt[nbs[t]];
    for (int i = t; i < NV * NW * NC; i += 256) {
        int v = i / (NW * NC), j = i % (NW * NC);
        Sm.kall[v][j] = g_kaff[nbs[j >> 8]][v][b][j & 255];
    }
    for (int j = t; j < NW * NC; j += 256) Sm.vj[j] = g_valid[nbs[j >> 8]][j & 255];
    for (int i = t; i < NV * 64; i += 256) {
        int v = i >> 6, ii = i & 63;
        Sm.qvI[v][ii] = g_qaff[e][v][b][i0 + ii] * invT;
    }
    if (t < 64) { Sm.idxs[t] = g_idx[e][i0 + t]; Sm.vld[t] = g_valid[e][i0 + t]; }
    if (t < NV) {
        float mx = -INFINITY, mn = INFINITY;
        for (int n = 0; n < NW; n++) {
            mx = fmaxf(mx, g_kmax[nbs[n]][t][b]);
            mn = fminf(mn, g_kmin[nbs[n]][t][b]);
        }
        Sm.kmaxc[t] = mx;
        Sm.kminc[t] = mn;
    }
    __syncthreads();

    // ---- Pass A: per-row per-direction Z ----
    int ii = t & 63, grp = t >> 6;
    for (int v = 0; v < NV; v++) {
        float q = Sm.qvI[v][ii];
        float m = fmaxf(q * Sm.kmaxc[v], q * Sm.kminc[v]);
        if (grp == 0) Sm.miv[v][ii] = m;
        float z = 0.f;
        int jb = grp * 192;
        for (int j = jb; j < jb + 192; j++) {
            if (Sm.vj[j]) z += expf(q * Sm.kall[v][j] - m);
        }
        Sm.zp[ii][grp] = z;
        __syncthreads();
        if (grp == 0) {
            float Z = Sm.zp[ii][0] + Sm.zp[ii][1] + Sm.zp[ii][2] + Sm.zp[ii][3];
            Sm.cw[v][ii] = (Z > 0.f) ? (g_wdir[v] / Z) : 0.f;
        }
        __syncthreads();
    }

    // ---- Pass B: combined-weight GEMM  out(64x128) = Wcomb(64x768) @ Vcat(768x128) ----
    int tx = t & 15, ty = t >> 4;
    float acc[4][8];
#pragma unroll
    for (int r = 0; r < 4; r++)
#pragma unroll
        for (int c = 0; c < 8; c++) acc[r][c] = 0.f;

    for (int ch = 0; ch < 12; ch++) {
        int jb = ch * 64;
        int n  = jb >> 8;
        int jl = jb & 255;
        if (jl >= Sm.cnt3[n]) continue;   // whole j-chunk invalid -> weights all 0

        // load V chunk (64 x 128)
        {
            int row = t >> 2, part = t & 3;
            const float4* src = reinterpret_cast<const float4*>(&g_vbuf[nbs[n]][b][jl + row][part * 32]);
            float4* dst = reinterpret_cast<float4*>(&Sm.vchunk[row][part * 32]);
#pragma unroll
            for (int q8 = 0; q8 < 8; q8++) dst[q8] = src[q8];
        }
        // combined weights W[j][i] = sum_v cw_iv * exp(qI_iv * k_jv - m_iv)
        {
            int wii = t & 63, jg = t >> 6;
            float qr[NV], mr[NV], cwr[NV];
#pragma unroll
            for (int v = 0; v < NV; v++) {
                qr[v]  = Sm.qvI[v][wii];
                mr[v]  = Sm.miv[v][wii];
                cwr[v] = Sm.cw[v][wii];
            }
#pragma unroll 4
            for (int jj = jg * 16; jj < jg * 16 + 16; jj++) {
                int j = jb + jj;
                float wv = 0.f;
                if (Sm.vj[j]) {
#pragma unroll
                    for (int v = 0; v < NV; v++)
                        wv += cwr[v] * expf(qr[v] * Sm.kall[v][j] - mr[v]);
                }
                Sm.wsub[jj][wii] = wv;
            }
        }
        __syncthreads();
        // GEMM 64x128 += wsub(64x64)^T-ish @ vchunk(64x128)
#pragma unroll 8
        for (int k = 0; k < 64; k++) {
            float4 af = *reinterpret_cast<const float4*>(&Sm.wsub[k][ty * 4]);
            float4 b0 = *reinterpret_cast<const float4*>(&Sm.vchunk[k][tx * 8]);
            float4 b1 = *reinterpret_cast<const float4*>(&Sm.vchunk[k][tx * 8 + 4]);
            float av[4] = {af.x, af.y, af.z, af.w};
            float bv[8] = {b0.x, b0.y, b0.z, b0.w, b1.x, b1.y, b1.z, b1.w};
#pragma unroll
            for (int r = 0; r < 4; r++)
#pragma unroll
                for (int c = 0; c < 8; c++) acc[r][c] += av[r] * bv[c];
        }
        __syncthreads();
    }

    // write only valid rows (each valid token belongs to exactly one expert -> race-free)
#pragma unroll
    for (int r = 0; r < 4; r++) {
        int lii = ty * 4 + r;
        if (Sm.vld[lii]) {
            int pos = Sm.idxs[lii];
            float* dst = out + ((size_t)b * NP + pos) * NDM + tx * 8;
            reinterpret_cast<float4*>(dst)[0] = make_float4(acc[r][0], acc[r][1], acc[r][2], acc[r][3]);
            reinterpret_cast<float4*>(dst)[1] = make_float4(acc[r][4], acc[r][5], acc[r][6], acc[r][7]);
        }
    }
}

// ---------------- launch ----------------
extern "C" void kernel_launch(void* const* d_in, const int* in_sizes, int n_in,
                              void* d_out, int out_size)
{
    const float* tokens  = (const float*)d_in[0];
    const float* fingerp = (const float*)d_in[1];
    const float* alpha   = (const float*)d_in[2];
    const float* gw1     = (const float*)d_in[3];
    const float* gb1     = (const float*)d_in[4];
    const float* gw2     = (const float*)d_in[5];
    const float* gb2     = (const float*)d_in[6];
    const float* q_w     = (const float*)d_in[7];
    const float* k_w     = (const float*)d_in[8];
    const float* v_w     = (const float*)d_in[9];
    const float* penta   = (const float*)d_in[10];
    const float* fusion  = (const float*)d_in[11];
    const float* temp    = (const float*)d_in[12];
    float* out = (float*)d_out;

    static bool attr_done = false;
    (void)attr_done;
    cudaFuncSetAttribute(k_featproc, cudaFuncAttributeMaxDynamicSharedMemorySize, (int)sizeof(Smem2));
    cudaFuncSetAttribute(k_attn,     cudaFuncAttributeMaxDynamicSharedMemorySize, (int)sizeof(Smem3));

    k_setup<<<NE, 256>>>(alpha, penta, fusion, q_w, k_w, temp);
    k_dispatch<<<NE, 256>>>(fingerp);
    int n4 = out_size / 4;
    k_zero<<<(n4 + 255) / 256, 256>>>(out, n4);
    k_featproc<<<dim3(NE, NB), 256, sizeof(Smem2)>>>(tokens, gw1, gb1, gw2, gb2, v_w);
    k_attn<<<dim3(NE, NB, 4), 256, sizeof(Smem3)>>>(out);
}

// round 9
// speedup vs baseline: 2.4387x; 2.4387x over previous
#include <cuda_runtime.h>
#include <math.h>
#include <stdint.h>

#define NE 16
#define NS 64
#define NDM 128
#define NP 2048
#define NB 8
#define NC 256
#define NW 3
#define NV 5

typedef unsigned long long ull;

// ---------------- global scratch ----------------
__device__ int   g_routes[NE][NW];
__device__ float g_wdir[NV];
__device__ float g_aw[NE];
__device__ float g_invT;
__device__ float g_qd[NE][NS][NV];
__device__ float g_kd[NE][NS][NV];
__device__ int   g_idx[NE][NC];
__device__ int   g_cnt[NE];
__device__ float g_qaff[NE][NV][NB][NC];
__device__ float g_kaff[NE][NV][NB][NC];
__device__ float g_kmin[NE][NV][NB][2];
__device__ float g_kmax[NE][NV][NB][2];
__device__ float g_vbuf[NE][NB][NC][NDM];

// ---------------- helpers ----------------
__device__ __forceinline__ float ex2f(float x) {
    float r; asm("ex2.approx.ftz.f32 %0, %1;" : "=f"(r) : "f"(x)); return r;
}
__device__ __forceinline__ float lg2f_(float x) {
    float r; asm("lg2.approx.f32 %0, %1;" : "=f"(r) : "f"(x)); return r;
}
__device__ __forceinline__ ull fma2(ull a, ull b, ull c) {
    ull d; asm("fma.rn.f32x2 %0, %1, %2, %3;" : "=l"(d) : "l"(a), "l"(b), "l"(c)); return d;
}
__device__ __forceinline__ ull pack2(float lo, float hi) {
    ull d; asm("mov.b64 %0, {%1, %2};" : "=l"(d) : "f"(lo), "f"(hi)); return d;
}
__device__ __forceinline__ float2 unpack2(ull v) {
    float2 r; asm("mov.b64 {%0, %1}, %2;" : "=f"(r.x), "=f"(r.y) : "l"(v)); return r;
}
__device__ __forceinline__ float geluf(float x) {
    float x3 = x * x * x;
    return 0.5f * x * (1.0f + tanhf(0.7978845608028654f * (x + 0.044715f * x3)));
}

// ---------------- K0: setup ----------------
__global__ __launch_bounds__(256) void k_setup(
    const float* __restrict__ alpha, const float* __restrict__ penta,
    const float* __restrict__ fusion_w, const float* __restrict__ q_w,
    const float* __restrict__ k_w, const float* __restrict__ temp)
{
    int e = blockIdx.x, t = threadIdx.x;
    __shared__ float dirs[NV][NDM];
    __shared__ float rn[NV];
    int w = t >> 5, lane = t & 31;
    if (w < NV) {
        float s = 0.f;
        for (int d = lane; d < NDM; d += 32) {
            float x = penta[(e * NV + w) * NDM + d];
            s += x * x;
        }
        for (int off = 16; off; off >>= 1) s += __shfl_xor_sync(0xffffffffu, s, off);
        if (lane == 0) rn[w] = rsqrtf(s);
    }
    __syncthreads();
    for (int i = t; i < NV * NDM; i += 256) {
        int v = i >> 7, d = i & 127;
        dirs[v][d] = penta[(e * NV + v) * NDM + d] * rn[v];
    }
    __syncthreads();
    for (int i = t; i < NS * NV; i += 256) {
        int s = i / NV, v = i % NV;
        float aq = 0.f, ak = 0.f;
        for (int d = 0; d < NDM; d++) {
            float dd = dirs[v][d];
            aq += q_w[(e * NS + s) * NDM + d] * dd;
            ak += k_w[(e * NS + s) * NDM + d] * dd;
        }
        g_qd[e][s][v] = aq;
        g_kd[e][s][v] = ak;
    }
    if (e == 0) {
        if (t < NE) g_aw[t] = 1.f / (1.f + expf(-alpha[t]));
        if (t == 0) {
            g_invT = 1.0f / temp[0];
            float mx = -1e30f;
            for (int i = 0; i < NV; i++) mx = fmaxf(mx, fusion_w[i]);
            float ex[NV], sm = 0.f;
            for (int i = 0; i < NV; i++) { ex[i] = expf(fusion_w[i] - mx); sm += ex[i]; }
            for (int i = 0; i < NV; i++) g_wdir[i] = ex[i] / sm;
            float coords[NE];
            for (int i = 0; i < NE; i++) {
                double x = (double)i / 15.0;
                x = fmax(1e-6, fmin(x, 1.0 - 1e-6));
                double val = 0.0, fac = 0.5;
                for (int k = 0; k < 8; k++) {
                    x *= 3.0;
                    int d = (int)x;
                    x -= (double)d;
                    if (d == 2) val += fac;
                    fac *= 0.5;
                }
                coords[i] = (float)val;
            }
            for (int ee = 0; ee < NE; ee++) {
                float key[NE]; int ord[NE];
                for (int i = 0; i < NE; i++) { key[i] = fabsf(coords[i] - coords[ee]); ord[i] = i; }
                for (int i = 1; i < NE; i++) {
                    float kv = key[i]; int ov = ord[i]; int j = i - 1;
                    while (j >= 0 && key[j] > kv) { key[j + 1] = key[j]; ord[j + 1] = ord[j]; j--; }
                    key[j + 1] = kv; ord[j + 1] = ov;
                }
                for (int wv = 0; wv < NW; wv++) g_routes[ee][wv] = ord[wv];
            }
        }
    }
}

// ---------------- K1: dispatch (warp ballot compaction, warp = expert) ----------------
__global__ __launch_bounds__(512) void k_dispatch(const float* __restrict__ fp)
{
    __shared__ float sf[NP];
    int t = threadIdx.x;
    for (int i = t; i < NP; i += 512) sf[i] = fp[i];
    __syncthreads();
    int w = t >> 5, l = t & 31;
    float lo = (float)w / 16.0f, hi = (float)(w + 1) / 16.0f;
    unsigned lmask = (1u << l) - 1u;
    // pass 1: valid tokens in index order
    int cnt = 0;
    for (int base = 0; base < NP; base += 32) {
        float f = sf[base + l];
        bool m = (f >= lo) && ((w == NE - 1) ? (f <= hi) : (f < hi));
        unsigned bal = __ballot_sync(0xffffffffu, m);
        if (m) {
            int pos = cnt + __popc(bal & lmask);
            if (pos < NC) g_idx[w][pos] = base + l;
        }
        cnt += __popc(bal);
    }
    int vcnt = min(cnt, NC);
    if (l == 0) g_cnt[w] = vcnt;
    // pass 2: invalid tokens fill the remainder (index order)
    cnt = vcnt;
    for (int base = 0; base < NP && cnt < NC; base += 32) {
        float f = sf[base + l];
        bool m = (f >= lo) && ((w == NE - 1) ? (f <= hi) : (f < hi));
        bool im = !m;
        unsigned bal = __ballot_sync(0xffffffffu, im);
        if (im) {
            int pos = cnt + __popc(bal & lmask);
            if (pos < NC) g_idx[w][pos] = base + l;
        }
        cnt += __popc(bal);
    }
}

// ---------------- K zero output ----------------
__global__ __launch_bounds__(256) void k_zero(float* __restrict__ out, int n4)
{
    int i = blockIdx.x * blockDim.x + threadIdx.x;
    if (i < n4) reinterpret_cast<float4*>(out)[i] = make_float4(0.f, 0.f, 0.f, 0.f);
}

// ---------------- K2: gather + gate + affinities + V projection ----------------
// grid (E, B, 2): each block does 128 rows of the 256-row tile.
struct __align__(16) Smem2 {
    float featsT[NS][132];   // [s][local row], 33792 B
    float vw[NS][NDM];       // 32768 B
    float qkd[NS][12];       // qd[0..4], kd[5..9]
    float w1[NS][16];
    float b1[16];
    float w2[16];
    float red[2][NV][4];     // [max/min][v][warp]
    int   idxs[128];
    float b2;
};

__global__ __launch_bounds__(256) void k_featproc(
    const float* __restrict__ tokens, const float* __restrict__ gw1,
    const float* __restrict__ gb1, const float* __restrict__ gw2,
    const float* __restrict__ gb2, const float* __restrict__ vwg)
{
    extern __shared__ char smraw[];
    Smem2& Sm = *reinterpret_cast<Smem2*>(smraw);
    int e = blockIdx.x, b = blockIdx.y, half = blockIdx.z, t = threadIdx.x;
    int i0 = half * 128;
    int cnt = g_cnt[e];
    int nvloc = cnt - i0;
    if (nvloc < 0) nvloc = 0;
    if (nvloc > 128) nvloc = 128;

    if (nvloc == 0) {
        // fast path: everything in this half is invalid -> write safe zeros
        float4 z4 = make_float4(0.f, 0.f, 0.f, 0.f);
        float4* vb = reinterpret_cast<float4*>(&g_vbuf[e][b][i0][0]);
        for (int idx = t; idx < 128 * 32; idx += 256) vb[idx] = z4;
        for (int idx = t; idx < NV * 128; idx += 256) {
            int v = idx >> 7, ii = idx & 127;
            g_qaff[e][v][b][i0 + ii] = 0.f;
            g_kaff[e][v][b][i0 + ii] = 0.f;
        }
        if (t < NV) {
            g_kmax[e][t][b][half] = -INFINITY;
            g_kmin[e][t][b][half] = INFINITY;
        }
        return;
    }

    // ---- loads ----
    if (t < 128) Sm.idxs[t] = g_idx[e][i0 + t];
    for (int idx = t; idx < NS * 16; idx += 256) Sm.w1[idx >> 4][idx & 15] = gw1[e * NS * 16 + idx];
    if (t < 16) { Sm.b1[t] = gb1[e * 16 + t]; Sm.w2[t] = gw2[e * 16 + t]; }
    if (t == 0) Sm.b2 = gb2[e];
    for (int idx = t; idx < NS * NV; idx += 256) {
        int s = idx / NV, v = idx % NV;
        Sm.qkd[s][v]     = g_qd[e][s][v];
        Sm.qkd[s][5 + v] = g_kd[e][s][v];
    }
    {
        const float4* src = reinterpret_cast<const float4*>(vwg + e * NS * NDM);
        float4* dst = reinterpret_cast<float4*>(&Sm.vw[0][0]);
        for (int idx = t; idx < NS * NDM / 4; idx += 256) dst[idx] = src[idx];
    }
    __syncthreads();

    // ---- gather (warp per row); zero rows beyond cnt ----
    {
        int w = t >> 5, l = t & 31;
        for (int r = w; r < 128; r += 8) {
            float2 v2 = make_float2(0.f, 0.f);
            if (r < nvloc) {
                const float* src = tokens + ((size_t)b * NP + Sm.idxs[r]) * 1024 + e * NS;
                v2 = reinterpret_cast<const float2*>(src)[l];
            }
            Sm.featsT[2 * l][r]     = v2.x;
            Sm.featsT[2 * l + 1][r] = v2.y;
        }
    }
    __syncthreads();

    // ---- gate + scale + affinities (t < 128, row t) ----
    float aw = g_aw[e];
    if (t < 128) {
        int i = t;
        ull h2[8];
#pragma unroll
        for (int k = 0; k < 8; k++) h2[k] = pack2(Sm.b1[2 * k], Sm.b1[2 * k + 1]);
        for (int s = 0; s < NS; s++) {
            float f = Sm.featsT[s][i];
            ull f2 = pack2(f, f);
            const ulonglong2* wp = reinterpret_cast<const ulonglong2*>(&Sm.w1[s][0]);
#pragma unroll
            for (int j = 0; j < 4; j++) {
                ulonglong2 wv = wp[j];
                h2[2 * j]     = fma2(f2, wv.x, h2[2 * j]);
                h2[2 * j + 1] = fma2(f2, wv.y, h2[2 * j + 1]);
            }
        }
        float o = Sm.b2;
#pragma unroll
        for (int k = 0; k < 8; k++) {
            float2 hh = unpack2(h2[k]);
            o += geluf(hh.x) * Sm.w2[2 * k] + geluf(hh.y) * Sm.w2[2 * k + 1];
        }
        float gsig  = 1.f / (1.f + __expf(-o));
        float scale = gsig * aw + (1.f - aw);

        float qa[NV], ka[NV];
#pragma unroll
        for (int v = 0; v < NV; v++) { qa[v] = 0.f; ka[v] = 0.f; }
        for (int s = 0; s < NS; s++) {
            float f = Sm.featsT[s][i] * scale;
            Sm.featsT[s][i] = f;
            float4 c0 = *reinterpret_cast<const float4*>(&Sm.qkd[s][0]);
            float4 c1 = *reinterpret_cast<const float4*>(&Sm.qkd[s][4]);
            float4 c2 = *reinterpret_cast<const float4*>(&Sm.qkd[s][8]);
            qa[0] += f * c0.x; qa[1] += f * c0.y; qa[2] += f * c0.z; qa[3] += f * c0.w;
            qa[4] += f * c1.x;
            ka[0] += f * c1.y; ka[1] += f * c1.z; ka[2] += f * c1.w;
            ka[3] += f * c2.x; ka[4] += f * c2.y;
        }
        bool vl = (i < nvloc);
#pragma unroll
        for (int v = 0; v < NV; v++) {
            g_qaff[e][v][b][i0 + i] = qa[v];
            g_kaff[e][v][b][i0 + i] = ka[v];
        }
        int w = t >> 5, lane = t & 31;
#pragma unroll
        for (int v = 0; v < NV; v++) {
            float kmx = vl ? ka[v] : -INFINITY;
            float kmn = vl ? ka[v] :  INFINITY;
            for (int off = 16; off; off >>= 1) {
                kmx = fmaxf(kmx, __shfl_xor_sync(0xffffffffu, kmx, off));
                kmn = fminf(kmn, __shfl_xor_sync(0xffffffffu, kmn, off));
            }
            if (lane == 0) { Sm.red[0][v][w] = kmx; Sm.red[1][v][w] = kmn; }
        }
    }
    __syncthreads();
    if (t < NV) {
        float mx = -INFINITY, mn = INFINITY;
        for (int w = 0; w < 4; w++) {
            mx = fmaxf(mx, Sm.red[0][t][w]);
            mn = fminf(mn, Sm.red[1][t][w]);
        }
        g_kmax[e][t][b][half] = mx;
        g_kmin[e][t][b][half] = mn;
    }

    // ---- V GEMM: 128x128 = featsT^T(128x64) @ vw(64x128), f32x2 ----
    int lane = t & 31, wi = t >> 5;
    for (int pass = 0; pass < 2; pass++) {
        int r0 = pass * 64 + wi * 8;
        ull acc[4][4];
#pragma unroll
        for (int rp = 0; rp < 4; rp++)
#pragma unroll
            for (int c = 0; c < 4; c++) acc[rp][c] = 0ull;
#pragma unroll 4
        for (int k = 0; k < NS; k++) {
            ulonglong2 a01 = *reinterpret_cast<const ulonglong2*>(&Sm.featsT[k][r0]);
            ulonglong2 a23 = *reinterpret_cast<const ulonglong2*>(&Sm.featsT[k][r0 + 4]);
            float4 bv = *reinterpret_cast<const float4*>(&Sm.vw[k][lane * 4]);
            ull ar[4] = {a01.x, a01.y, a23.x, a23.y};
            ull bc[4] = {pack2(bv.x, bv.x), pack2(bv.y, bv.y), pack2(bv.z, bv.z), pack2(bv.w, bv.w)};
#pragma unroll
            for (int rp = 0; rp < 4; rp++)
#pragma unroll
                for (int c = 0; c < 4; c++) acc[rp][c] = fma2(ar[rp], bc[c], acc[rp][c]);
        }
#pragma unroll
        for (int rp = 0; rp < 4; rp++) {
            float2 u0 = unpack2(acc[rp][0]), u1 = unpack2(acc[rp][1]);
            float2 u2 = unpack2(acc[rp][2]), u3 = unpack2(acc[rp][3]);
            int row = r0 + rp * 2;
            float* d0 = &g_vbuf[e][b][i0 + row][lane * 4];
            float* d1 = &g_vbuf[e][b][i0 + row + 1][lane * 4];
            *reinterpret_cast<float4*>(d0) = make_float4(u0.x, u1.x, u2.x, u3.x);
            *reinterpret_cast<float4*>(d1) = make_float4(u0.y, u1.y, u2.y, u3.y);
        }
    }
}

// ---------------- K3: fused multi-direction attention ----------------
struct __align__(16) Smem3 {
    float vchunk[32][132];   // 16896
    float wsub[32][68];      // 8704
    float kall[NV][NW * NC]; // 15360
    float kbias[NW * NC];    // 3072
    float q2[NV][64];
    float m2[NV][64];
    float Cc[NV][64];
    float zp[NV][4][64];
    float kmaxc[NV];
    float kminc[NV];
    float wdirs[NV];
    int   idxs[64];
    int   cnt3[NW];
};

__global__ __launch_bounds__(256) void k_attn(float* __restrict__ out)
{
    int e = blockIdx.x, b = blockIdx.y, it = blockIdx.z, t = threadIdx.x;
    int cnte = g_cnt[e];
    int i0 = it * 64;
    if (i0 >= cnte) return;

    extern __shared__ char smraw[];
    Smem3& Sm = *reinterpret_cast<Smem3*>(smraw);

    int nbs[NW] = {g_routes[e][0], g_routes[e][1], g_routes[e][2]};

    if (t < NW) Sm.cnt3[t] = g_cnt[nbs[t]];
    if (t < NV) {
        Sm.wdirs[t] = g_wdir[t];
        float mx = -INFINITY, mn = INFINITY;
        for (int n = 0; n < NW; n++)
            for (int h = 0; h < 2; h++) {
                mx = fmaxf(mx, g_kmax[nbs[n]][t][b][h]);
                mn = fminf(mn, g_kmin[nbs[n]][t][b][h]);
            }
        Sm.kmaxc[t] = mx;
        Sm.kminc[t] = mn;
    }
    for (int idx = t; idx < 960; idx += 256) {
        int v = idx / 192, r = idx % 192, n = r >> 6, c4 = r & 63;
        float4 val = *reinterpret_cast<const float4*>(&g_kaff[nbs[n]][v][b][c4 * 4]);
        *reinterpret_cast<float4*>(&Sm.kall[v][n * 256 + c4 * 4]) = val;
    }
    float invTl2 = g_invT * 1.4426950408889634f;
    for (int idx = t; idx < NV * 64; idx += 256) {
        int v = idx >> 6, ii = idx & 63;
        Sm.q2[v][ii] = g_qaff[e][v][b][i0 + ii] * invTl2;
    }
    if (t < 64) Sm.idxs[t] = g_idx[e][i0 + t];
    __syncthreads();
    for (int j = t; j < NW * NC; j += 256)
        Sm.kbias[j] = ((j & 255) < Sm.cnt3[j >> 8]) ? 0.f : -1e30f;
    __syncthreads();

    // ---- Pass A: per-(row, dir) normalizer in log2 domain ----
    {
        int ii = t & 63, grp = t >> 6;
#pragma unroll
        for (int v = 0; v < NV; v++) {
            float q = Sm.q2[v][ii];
            float m = fmaxf(q * Sm.kmaxc[v], q * Sm.kminc[v]);
            if (grp == 0) Sm.m2[v][ii] = m;
            float z = 0.f;
            int jb = grp * 192;
            for (int j4 = jb; j4 < jb + 192; j4 += 4) {
                float4 kb = *reinterpret_cast<const float4*>(&Sm.kbias[j4]);
                if (kb.x == 0.f) {   // validity is a prefix within each 4-group
                    float4 kv = *reinterpret_cast<const float4*>(&Sm.kall[v][j4]);
                    z += ex2f(fmaf(q, kv.x, kb.x - m));
                    z += ex2f(fmaf(q, kv.y, kb.y - m));
                    z += ex2f(fmaf(q, kv.z, kb.z - m));
                    z += ex2f(fmaf(q, kv.w, kb.w - m));
                }
            }
            Sm.zp[v][grp][ii] = z;
        }
    }
    __syncthreads();
    for (int idx = t; idx < NV * 64; idx += 256) {
        int v = idx / 64, iL = idx % 64;
        float Z = Sm.zp[v][0][iL] + Sm.zp[v][1][iL] + Sm.zp[v][2][iL] + Sm.zp[v][3][iL];
        Sm.Cc[v][iL] = (Z > 0.f) ? (lg2f_(Sm.wdirs[v] / Z) - Sm.m2[v][iL]) : -1e30f;
    }
    __syncthreads();

    // ---- Pass B: combined-weight GEMM in 32-row chunks, f32x2 ----
    int i = t & 63, jgrp = t >> 6;
    float q2r[NV], Cr[NV];
#pragma unroll
    for (int v = 0; v < NV; v++) { q2r[v] = Sm.q2[v][i]; Cr[v] = Sm.Cc[v][i]; }

    int lane = t & 31, w = t >> 5;
    ull acc[4][4];
#pragma unroll
    for (int rp = 0; rp < 4; rp++)
#pragma unroll
        for (int c = 0; c < 4; c++) acc[rp][c] = 0ull;

    for (int ch = 0; ch < 24; ch++) {
        int n = ch >> 3, jl = (ch & 7) * 32;
        int cn = Sm.cnt3[n];
        if (jl >= cn) continue;
        __syncthreads();   // previous chunk's GEMM reads done

        // load V chunk (32 x 128 f32) from L2-resident vbuf
        {
            const float4* vsrc = reinterpret_cast<const float4*>(&g_vbuf[nbs[n]][b][jl][0]);
#pragma unroll
            for (int k4 = 0; k4 < 4; k4++) {
                int idx = t + k4 * 256;
                int row = idx >> 5, c4 = idx & 31;
                *reinterpret_cast<float4*>(&Sm.vchunk[row][c4 * 4]) = vsrc[idx];
            }
        }
        // combined weights W[j][i] = sum_v exp2(q2*k + C)
        {
#pragma unroll
            for (int jj = 0; jj < 8; jj++) {
                int jloc = jgrp * 8 + jj;
                int j = n * 256 + jl + jloc;
                float wv = 0.f;
#pragma unroll
                for (int v = 0; v < NV; v++)
                    wv += ex2f(fmaf(q2r[v], Sm.kall[v][j], Cr[v]));
                if (jl + jloc >= cn) wv = 0.f;
                Sm.wsub[jloc][i] = wv;
            }
        }
        __syncthreads();
        // GEMM: out(64x128) += wsub(32x64)^T-as-[k][i] @ vchunk(32x128)
#pragma unroll 4
        for (int k = 0; k < 32; k++) {
            ulonglong2 a01 = *reinterpret_cast<const ulonglong2*>(&Sm.wsub[k][w * 8]);
            ulonglong2 a23 = *reinterpret_cast<const ulonglong2*>(&Sm.wsub[k][w * 8 + 4]);
            float4 bv = *reinterpret_cast<const float4*>(&Sm.vchunk[k][lane * 4]);
            ull ar[4] = {a01.x, a01.y, a23.x, a23.y};
            ull bc[4] = {pack2(bv.x, bv.x), pack2(bv.y, bv.y), pack2(bv.z, bv.z), pack2(bv.w, bv.w)};
#pragma unroll
            for (int rp = 0; rp < 4; rp++)
#pragma unroll
                for (int c = 0; c < 4; c++) acc[rp][c] = fma2(ar[rp], bc[c], acc[rp][c]);
        }
    }

    // ---- store valid rows (each token owned by exactly one expert) ----
#pragma unroll
    for (int rp = 0; rp < 4; rp++) {
        int row = w * 8 + rp * 2;
        float2 u0 = unpack2(acc[rp][0]), u1 = unpack2(acc[rp][1]);
        float2 u2 = unpack2(acc[rp][2]), u3 = unpack2(acc[rp][3]);
        if (i0 + row < cnte) {
            float* dst = out + ((size_t)b * NP + Sm.idxs[row]) * NDM + lane * 4;
            *reinterpret_cast<float4*>(dst) = make_float4(u0.x, u1.x, u2.x, u3.x);
        }
        if (i0 + row + 1 < cnte) {
            float* dst = out + ((size_t)b * NP + Sm.idxs[row + 1]) * NDM + lane * 4;
            *reinterpret_cast<float4*>(dst) = make_float4(u0.y, u1.y, u2.y, u3.y);
        }
    }
}

// ---------------- launch ----------------
extern "C" void kernel_launch(void* const* d_in, const int* in_sizes, int n_in,
                              void* d_out, int out_size)
{
    const float* tokens  = (const float*)d_in[0];
    const float* fingerp = (const float*)d_in[1];
    const float* alpha   = (const float*)d_in[2];
    const float* gw1     = (const float*)d_in[3];
    const float* gb1     = (const float*)d_in[4];
    const float* gw2     = (const float*)d_in[5];
    const float* gb2     = (const float*)d_in[6];
    const float* q_w     = (const float*)d_in[7];
    const float* k_w     = (const float*)d_in[8];
    const float* v_w     = (const float*)d_in[9];
    const float* penta   = (const float*)d_in[10];
    const float* fusion  = (const float*)d_in[11];
    const float* temp    = (const float*)d_in[12];
    float* out = (float*)d_out;

    cudaFuncSetAttribute(k_featproc, cudaFuncAttributeMaxDynamicSharedMemorySize, (int)sizeof(Smem2));
    cudaFuncSetAttribute(k_attn,     cudaFuncAttributeMaxDynamicSharedMemorySize, (int)sizeof(Smem3));

    k_setup<<<NE, 256>>>(alpha, penta, fusion, q_w, k_w, temp);
    k_dispatch<<<1, 512>>>(fingerp);
    int n4 = out_size / 4;
    k_zero<<<(n4 + 255) / 256, 256>>>(out, n4);
    k_featproc<<<dim3(NE, NB, 2), 256, sizeof(Smem2)>>>(tokens, gw1, gb1, gw2, gb2, v_w);
    k_attn<<<dim3(NE, NB, 4), 256, sizeof(Smem3)>>>(out);
}

// round 10
// speedup vs baseline: 2.4404x; 1.0007x over previous
#include <cuda_runtime.h>
#include <math.h>
#include <stdint.h>

#define NE 16
#define NS 64
#define NDM 128
#define NP 2048
#define NB 8
#define NC 256
#define NW 3
#define NV 5

typedef unsigned long long ull;

// ---------------- global scratch ----------------
__device__ int   g_routes[NE][NW];
__device__ float g_wdir[NV];
__device__ float g_aw[NE];
__device__ float g_invT;
__device__ float g_qd[NE][NS][NV];
__device__ float g_kd[NE][NS][NV];
__device__ int   g_idx[NE][NC];
__device__ int   g_cnt[NE];
__device__ float g_qaff[NE][NV][NB][NC];
__device__ float g_kaff[NE][NV][NB][NC];
__device__ float g_kmin[NE][NV][NB][2];
__device__ float g_kmax[NE][NV][NB][2];
__device__ float g_vbuf[NE][NB][NC][NDM];

// ---------------- helpers ----------------
__device__ __forceinline__ float ex2f(float x) {
    float r; asm("ex2.approx.ftz.f32 %0, %1;" : "=f"(r) : "f"(x)); return r;
}
__device__ __forceinline__ float lg2f_(float x) {
    float r; asm("lg2.approx.f32 %0, %1;" : "=f"(r) : "f"(x)); return r;
}
__device__ __forceinline__ ull fma2(ull a, ull b, ull c) {
    ull d; asm("fma.rn.f32x2 %0, %1, %2, %3;" : "=l"(d) : "l"(a), "l"(b), "l"(c)); return d;
}
__device__ __forceinline__ ull pack2(float lo, float hi) {
    ull d; asm("mov.b64 %0, {%1, %2};" : "=l"(d) : "f"(lo), "f"(hi)); return d;
}
__device__ __forceinline__ float2 unpack2(ull v) {
    float2 r; asm("mov.b64 {%0, %1}, %2;" : "=f"(r.x), "=f"(r.y) : "l"(v)); return r;
}
__device__ __forceinline__ float geluf(float x) {
    float x3 = x * x * x;
    return 0.5f * x * (1.0f + tanhf(0.7978845608028654f * (x + 0.044715f * x3)));
}

// ---------------- K0: setup ----------------
__global__ __launch_bounds__(256) void k_setup(
    const float* __restrict__ alpha, const float* __restrict__ penta,
    const float* __restrict__ fusion_w, const float* __restrict__ q_w,
    const float* __restrict__ k_w, const float* __restrict__ temp)
{
    int e = blockIdx.x, t = threadIdx.x;
    __shared__ float dirs[NV][NDM];
    __shared__ float rn[NV];
    int w = t >> 5, lane = t & 31;
    if (w < NV) {
        float s = 0.f;
        for (int d = lane; d < NDM; d += 32) {
            float x = penta[(e * NV + w) * NDM + d];
            s += x * x;
        }
        for (int off = 16; off; off >>= 1) s += __shfl_xor_sync(0xffffffffu, s, off);
        if (lane == 0) rn[w] = rsqrtf(s);
    }
    __syncthreads();
    for (int i = t; i < NV * NDM; i += 256) {
        int v = i >> 7, d = i & 127;
        dirs[v][d] = penta[(e * NV + v) * NDM + d] * rn[v];
    }
    __syncthreads();
    for (int i = t; i < NS * NV; i += 256) {
        int s = i / NV, v = i % NV;
        float aq = 0.f, ak = 0.f;
        for (int d = 0; d < NDM; d++) {
            float dd = dirs[v][d];
            aq += q_w[(e * NS + s) * NDM + d] * dd;
            ak += k_w[(e * NS + s) * NDM + d] * dd;
        }
        g_qd[e][s][v] = aq;
        g_kd[e][s][v] = ak;
    }
    if (e == 0) {
        if (t < NE) g_aw[t] = 1.f / (1.f + expf(-alpha[t]));
        if (t == 0) {
            g_invT = 1.0f / temp[0];
            float mx = -1e30f;
            for (int i = 0; i < NV; i++) mx = fmaxf(mx, fusion_w[i]);
            float ex[NV], sm = 0.f;
            for (int i = 0; i < NV; i++) { ex[i] = expf(fusion_w[i] - mx); sm += ex[i]; }
            for (int i = 0; i < NV; i++) g_wdir[i] = ex[i] / sm;
            float coords[NE];
            for (int i = 0; i < NE; i++) {
                double x = (double)i / 15.0;
                x = fmax(1e-6, fmin(x, 1.0 - 1e-6));
                double val = 0.0, fac = 0.5;
                for (int k = 0; k < 8; k++) {
                    x *= 3.0;
                    int d = (int)x;
                    x -= (double)d;
                    if (d == 2) val += fac;
                    fac *= 0.5;
                }
                coords[i] = (float)val;
            }
            for (int ee = 0; ee < NE; ee++) {
                float key[NE]; int ord[NE];
                for (int i = 0; i < NE; i++) { key[i] = fabsf(coords[i] - coords[ee]); ord[i] = i; }
                for (int i = 1; i < NE; i++) {
                    float kv = key[i]; int ov = ord[i]; int j = i - 1;
                    while (j >= 0 && key[j] > kv) { key[j + 1] = key[j]; ord[j + 1] = ord[j]; j--; }
                    key[j + 1] = kv; ord[j + 1] = ov;
                }
                for (int wv = 0; wv < NW; wv++) g_routes[ee][wv] = ord[wv];
            }
        }
    }
}

// ---------------- K1: dispatch (warp ballot compaction, warp = expert) ----------------
__global__ __launch_bounds__(512) void k_dispatch(const float* __restrict__ fp)
{
    __shared__ float sf[NP];
    int t = threadIdx.x;
    for (int i = t; i < NP; i += 512) sf[i] = fp[i];
    __syncthreads();
    int w = t >> 5, l = t & 31;
    float lo = (float)w / 16.0f, hi = (float)(w + 1) / 16.0f;
    unsigned lmask = (1u << l) - 1u;
    // pass 1: valid tokens in index order
    int cnt = 0;
    for (int base = 0; base < NP; base += 32) {
        float f = sf[base + l];
        bool m = (f >= lo) && ((w == NE - 1) ? (f <= hi) : (f < hi));
        unsigned bal = __ballot_sync(0xffffffffu, m);
        if (m) {
            int pos = cnt + __popc(bal & lmask);
            if (pos < NC) g_idx[w][pos] = base + l;
        }
        cnt += __popc(bal);
    }
    int vcnt = min(cnt, NC);
    if (l == 0) g_cnt[w] = vcnt;
    // pass 2: invalid tokens fill the remainder (index order)
    cnt = vcnt;
    for (int base = 0; base < NP && cnt < NC; base += 32) {
        float f = sf[base + l];
        bool m = (f >= lo) && ((w == NE - 1) ? (f <= hi) : (f < hi));
        bool im = !m;
        unsigned bal = __ballot_sync(0xffffffffu, im);
        if (im) {
            int pos = cnt + __popc(bal & lmask);
            if (pos < NC) g_idx[w][pos] = base + l;
        }
        cnt += __popc(bal);
    }
}

// ---------------- K zero output ----------------
__global__ __launch_bounds__(256) void k_zero(float* __restrict__ out, int n4)
{
    int i = blockIdx.x * blockDim.x + threadIdx.x;
    if (i < n4) reinterpret_cast<float4*>(out)[i] = make_float4(0.f, 0.f, 0.f, 0.f);
}

// ---------------- K2: gather + gate + affinities + V projection ----------------
// grid (E, B, 2): each block does 128 rows of the 256-row tile.
struct __align__(16) Smem2 {
    float featsT[NS][132];   // [s][local row], 33792 B
    float vw[NS][NDM];       // 32768 B
    float qkd[NS][12];       // qd[0..4], kd[5..9]
    float w1[NS][16];
    float b1[16];
    float w2[16];
    float red[2][NV][4];     // [max/min][v][warp]
    int   idxs[128];
    float b2;
};

__global__ __launch_bounds__(256) void k_featproc(
    const float* __restrict__ tokens, const float* __restrict__ gw1,
    const float* __restrict__ gb1, const float* __restrict__ gw2,
    const float* __restrict__ gb2, const float* __restrict__ vwg)
{
    extern __shared__ char smraw[];
    Smem2& Sm = *reinterpret_cast<Smem2*>(smraw);
    int e = blockIdx.x, b = blockIdx.y, half = blockIdx.z, t = threadIdx.x;
    int i0 = half * 128;
    int cnt = g_cnt[e];
    int nvloc = cnt - i0;
    if (nvloc < 0) nvloc = 0;
    if (nvloc > 128) nvloc = 128;

    if (nvloc == 0) {
        // fast path: everything in this half is invalid -> write safe zeros
        float4 z4 = make_float4(0.f, 0.f, 0.f, 0.f);
        float4* vb = reinterpret_cast<float4*>(&g_vbuf[e][b][i0][0]);
        for (int idx = t; idx < 128 * 32; idx += 256) vb[idx] = z4;
        for (int idx = t; idx < NV * 128; idx += 256) {
            int v = idx >> 7, ii = idx & 127;
            g_qaff[e][v][b][i0 + ii] = 0.f;
            g_kaff[e][v][b][i0 + ii] = 0.f;
        }
        if (t < NV) {
            g_kmax[e][t][b][half] = -INFINITY;
            g_kmin[e][t][b][half] = INFINITY;
        }
        return;
    }

    // ---- loads ----
    if (t < 128) Sm.idxs[t] = g_idx[e][i0 + t];
    for (int idx = t; idx < NS * 16; idx += 256) Sm.w1[idx >> 4][idx & 15] = gw1[e * NS * 16 + idx];
    if (t < 16) { Sm.b1[t] = gb1[e * 16 + t]; Sm.w2[t] = gw2[e * 16 + t]; }
    if (t == 0) Sm.b2 = gb2[e];
    for (int idx = t; idx < NS * NV; idx += 256) {
        int s = idx / NV, v = idx % NV;
        Sm.qkd[s][v]     = g_qd[e][s][v];
        Sm.qkd[s][5 + v] = g_kd[e][s][v];
    }
    {
        const float4* src = reinterpret_cast<const float4*>(vwg + e * NS * NDM);
        float4* dst = reinterpret_cast<float4*>(&Sm.vw[0][0]);
        for (int idx = t; idx < NS * NDM / 4; idx += 256) dst[idx] = src[idx];
    }
    __syncthreads();

    // ---- gather (warp per row); zero rows beyond cnt ----
    {
        int w = t >> 5, l = t & 31;
        for (int r = w; r < 128; r += 8) {
            float2 v2 = make_float2(0.f, 0.f);
            if (r < nvloc) {
                const float* src = tokens + ((size_t)b * NP + Sm.idxs[r]) * 1024 + e * NS;
                v2 = reinterpret_cast<const float2*>(src)[l];
            }
            Sm.featsT[2 * l][r]     = v2.x;
            Sm.featsT[2 * l + 1][r] = v2.y;
        }
    }
    __syncthreads();

    // ---- gate + scale + affinities (t < 128, row t) ----
    float aw = g_aw[e];
    if (t < 128) {
        int i = t;
        ull h2[8];
#pragma unroll
        for (int k = 0; k < 8; k++) h2[k] = pack2(Sm.b1[2 * k], Sm.b1[2 * k + 1]);
        for (int s = 0; s < NS; s++) {
            float f = Sm.featsT[s][i];
            ull f2 = pack2(f, f);
            const ulonglong2* wp = reinterpret_cast<const ulonglong2*>(&Sm.w1[s][0]);
#pragma unroll
            for (int j = 0; j < 4; j++) {
                ulonglong2 wv = wp[j];
                h2[2 * j]     = fma2(f2, wv.x, h2[2 * j]);
                h2[2 * j + 1] = fma2(f2, wv.y, h2[2 * j + 1]);
            }
        }
        float o = Sm.b2;
#pragma unroll
        for (int k = 0; k < 8; k++) {
            float2 hh = unpack2(h2[k]);
            o += geluf(hh.x) * Sm.w2[2 * k] + geluf(hh.y) * Sm.w2[2 * k + 1];
        }
        float gsig  = 1.f / (1.f + __expf(-o));
        float scale = gsig * aw + (1.f - aw);

        float qa[NV], ka[NV];
#pragma unroll
        for (int v = 0; v < NV; v++) { qa[v] = 0.f; ka[v] = 0.f; }
        for (int s = 0; s < NS; s++) {
            float f = Sm.featsT[s][i] * scale;
            Sm.featsT[s][i] = f;
            float4 c0 = *reinterpret_cast<const float4*>(&Sm.qkd[s][0]);
            float4 c1 = *reinterpret_cast<const float4*>(&Sm.qkd[s][4]);
            float4 c2 = *reinterpret_cast<const float4*>(&Sm.qkd[s][8]);
            qa[0] += f * c0.x; qa[1] += f * c0.y; qa[2] += f * c0.z; qa[3] += f * c0.w;
            qa[4] += f * c1.x;
            ka[0] += f * c1.y; ka[1] += f * c1.z; ka[2] += f * c1.w;
            ka[3] += f * c2.x; ka[4] += f * c2.y;
        }
        bool vl = (i < nvloc);
#pragma unroll
        for (int v = 0; v < NV; v++) {
            g_qaff[e][v][b][i0 + i] = qa[v];
            g_kaff[e][v][b][i0 + i] = ka[v];
        }
        int w = t >> 5, lane = t & 31;
#pragma unroll
        for (int v = 0; v < NV; v++) {
            float kmx = vl ? ka[v] : -INFINITY;
            float kmn = vl ? ka[v] :  INFINITY;
            for (int off = 16; off; off >>= 1) {
                kmx = fmaxf(kmx, __shfl_xor_sync(0xffffffffu, kmx, off));
                kmn = fminf(kmn, __shfl_xor_sync(0xffffffffu, kmn, off));
            }
            if (lane == 0) { Sm.red[0][v][w] = kmx; Sm.red[1][v][w] = kmn; }
        }
    }
    __syncthreads();
    if (t < NV) {
        float mx = -INFINITY, mn = INFINITY;
        for (int w = 0; w < 4; w++) {
            mx = fmaxf(mx, Sm.red[0][t][w]);
            mn = fminf(mn, Sm.red[1][t][w]);
        }
        g_kmax[e][t][b][half] = mx;
        g_kmin[e][t][b][half] = mn;
    }

    // ---- V GEMM: 128x128 = featsT^T(128x64) @ vw(64x128), f32x2 ----
    int lane = t & 31, wi = t >> 5;
    for (int pass = 0; pass < 2; pass++) {
        int r0 = pass * 64 + wi * 8;
        ull acc[4][4];
#pragma unroll
        for (int rp = 0; rp < 4; rp++)
#pragma unroll
            for (int c = 0; c < 4; c++) acc[rp][c] = 0ull;
#pragma unroll 4
        for (int k = 0; k < NS; k++) {
            ulonglong2 a01 = *reinterpret_cast<const ulonglong2*>(&Sm.featsT[k][r0]);
            ulonglong2 a23 = *reinterpret_cast<const ulonglong2*>(&Sm.featsT[k][r0 + 4]);
            float4 bv = *reinterpret_cast<const float4*>(&Sm.vw[k][lane * 4]);
            ull ar[4] = {a01.x, a01.y, a23.x, a23.y};
            ull bc[4] = {pack2(bv.x, bv.x), pack2(bv.y, bv.y), pack2(bv.z, bv.z), pack2(bv.w, bv.w)};
#pragma unroll
            for (int rp = 0; rp < 4; rp++)
#pragma unroll
                for (int c = 0; c < 4; c++) acc[rp][c] = fma2(ar[rp], bc[c], acc[rp][c]);
        }
#pragma unroll
        for (int rp = 0; rp < 4; rp++) {
            float2 u0 = unpack2(acc[rp][0]), u1 = unpack2(acc[rp][1]);
            float2 u2 = unpack2(acc[rp][2]), u3 = unpack2(acc[rp][3]);
            int row = r0 + rp * 2;
            float* d0 = &g_vbuf[e][b][i0 + row][lane * 4];
            float* d1 = &g_vbuf[e][b][i0 + row + 1][lane * 4];
            *reinterpret_cast<float4*>(d0) = make_float4(u0.x, u1.x, u2.x, u3.x);
            *reinterpret_cast<float4*>(d1) = make_float4(u0.y, u1.y, u2.y, u3.y);
        }
    }
}

// ---------------- K3: fused multi-direction attention ----------------
struct __align__(16) Smem3 {
    float vchunk[32][132];   // 16896
    float wsub[32][68];      // 8704
    float kall[NV][NW * NC]; // 15360
    float kbias[NW * NC];    // 3072
    float q2[NV][64];
    float m2[NV][64];
    float Cc[NV][64];
    float zp[NV][4][64];
    float kmaxc[NV];
    float kminc[NV];
    float wdirs[NV];
    int   idxs[64];
    int   cnt3[NW];
};

__global__ __launch_bounds__(256) void k_attn(float* __restrict__ out)
{
    int e = blockIdx.x, b = blockIdx.y, it = blockIdx.z, t = threadIdx.x;
    int cnte = g_cnt[e];
    int i0 = it * 64;
    if (i0 >= cnte) return;

    extern __shared__ char smraw[];
    Smem3& Sm = *reinterpret_cast<Smem3*>(smraw);

    int nbs[NW] = {g_routes[e][0], g_routes[e][1], g_routes[e][2]};

    if (t < NW) Sm.cnt3[t] = g_cnt[nbs[t]];
    if (t < NV) {
        Sm.wdirs[t] = g_wdir[t];
        float mx = -INFINITY, mn = INFINITY;
        for (int n = 0; n < NW; n++)
            for (int h = 0; h < 2; h++) {
                mx = fmaxf(mx, g_kmax[nbs[n]][t][b][h]);
                mn = fminf(mn, g_kmin[nbs[n]][t][b][h]);
            }
        Sm.kmaxc[t] = mx;
        Sm.kminc[t] = mn;
    }
    for (int idx = t; idx < 960; idx += 256) {
        int v = idx / 192, r = idx % 192, n = r >> 6, c4 = r & 63;
        float4 val = *reinterpret_cast<const float4*>(&g_kaff[nbs[n]][v][b][c4 * 4]);
        *reinterpret_cast<float4*>(&Sm.kall[v][n * 256 + c4 * 4]) = val;
    }
    float invTl2 = g_invT * 1.4426950408889634f;
    for (int idx = t; idx < NV * 64; idx += 256) {
        int v = idx >> 6, ii = idx & 63;
        Sm.q2[v][ii] = g_qaff[e][v][b][i0 + ii] * invTl2;
    }
    if (t < 64) Sm.idxs[t] = g_idx[e][i0 + t];
    __syncthreads();
    for (int j = t; j < NW * NC; j += 256)
        Sm.kbias[j] = ((j & 255) < Sm.cnt3[j >> 8]) ? 0.f : -1e30f;
    __syncthreads();

    // ---- Pass A: per-(row, dir) normalizer in log2 domain ----
    {
        int ii = t & 63, grp = t >> 6;
#pragma unroll
        for (int v = 0; v < NV; v++) {
            float q = Sm.q2[v][ii];
            float m = fmaxf(q * Sm.kmaxc[v], q * Sm.kminc[v]);
            if (grp == 0) Sm.m2[v][ii] = m;
            float z = 0.f;
            int jb = grp * 192;
            for (int j4 = jb; j4 < jb + 192; j4 += 4) {
                float4 kb = *reinterpret_cast<const float4*>(&Sm.kbias[j4]);
                if (kb.x == 0.f) {   // validity is a prefix within each 4-group
                    float4 kv = *reinterpret_cast<const float4*>(&Sm.kall[v][j4]);
                    z += ex2f(fmaf(q, kv.x, kb.x - m));
                    z += ex2f(fmaf(q, kv.y, kb.y - m));
                    z += ex2f(fmaf(q, kv.z, kb.z - m));
                    z += ex2f(fmaf(q, kv.w, kb.w - m));
                }
            }
            Sm.zp[v][grp][ii] = z;
        }
    }
    __syncthreads();
    for (int idx = t; idx < NV * 64; idx += 256) {
        int v = idx / 64, iL = idx % 64;
        float Z = Sm.zp[v][0][iL] + Sm.zp[v][1][iL] + Sm.zp[v][2][iL] + Sm.zp[v][3][iL];
        Sm.Cc[v][iL] = (Z > 0.f) ? (lg2f_(Sm.wdirs[v] / Z) - Sm.m2[v][iL]) : -1e30f;
    }
    __syncthreads();

    // ---- Pass B: combined-weight GEMM in 32-row chunks, f32x2 ----
    int i = t & 63, jgrp = t >> 6;
    float q2r[NV], Cr[NV];
#pragma unroll
    for (int v = 0; v < NV; v++) { q2r[v] = Sm.q2[v][i]; Cr[v] = Sm.Cc[v][i]; }

    int lane = t & 31, w = t >> 5;
    ull acc[4][4];
#pragma unroll
    for (int rp = 0; rp < 4; rp++)
#pragma unroll
        for (int c = 0; c < 4; c++) acc[rp][c] = 0ull;

    for (int ch = 0; ch < 24; ch++) {
        int n = ch >> 3, jl = (ch & 7) * 32;
        int cn = Sm.cnt3[n];
        if (jl >= cn) continue;
        __syncthreads();   // previous chunk's GEMM reads done

        // load V chunk (32 x 128 f32) from L2-resident vbuf
        {
            const float4* vsrc = reinterpret_cast<const float4*>(&g_vbuf[nbs[n]][b][jl][0]);
#pragma unroll
            for (int k4 = 0; k4 < 4; k4++) {
                int idx = t + k4 * 256;
                int row = idx >> 5, c4 = idx & 31;
                *reinterpret_cast<float4*>(&Sm.vchunk[row][c4 * 4]) = vsrc[idx];
            }
        }
        // combined weights W[j][i] = sum_v exp2(q2*k + C)
        {
#pragma unroll
            for (int jj = 0; jj < 8; jj++) {
                int jloc = jgrp * 8 + jj;
                int j = n * 256 + jl + jloc;
                float wv = 0.f;
#pragma unroll
                for (int v = 0; v < NV; v++)
                    wv += ex2f(fmaf(q2r[v], Sm.kall[v][j], Cr[v]));
                if (jl + jloc >= cn) wv = 0.f;
                Sm.wsub[jloc][i] = wv;
            }
        }
        __syncthreads();
        // GEMM: out(64x128) += wsub(32x64)^T-as-[k][i] @ vchunk(32x128)
#pragma unroll 4
        for (int k = 0; k < 32; k++) {
            ulonglong2 a01 = *reinterpret_cast<const ulonglong2*>(&Sm.wsub[k][w * 8]);
            ulonglong2 a23 = *reinterpret_cast<const ulonglong2*>(&Sm.wsub[k][w * 8 + 4]);
            float4 bv = *reinterpret_cast<const float4*>(&Sm.vchunk[k][lane * 4]);
            ull ar[4] = {a01.x, a01.y, a23.x, a23.y};
            ull bc[4] = {pack2(bv.x, bv.x), pack2(bv.y, bv.y), pack2(bv.z, bv.z), pack2(bv.w, bv.w)};
#pragma unroll
            for (int rp = 0; rp < 4; rp++)
#pragma unroll
                for (int c = 0; c < 4; c++) acc[rp][c] = fma2(ar[rp], bc[c], acc[rp][c]);
        }
    }

    // ---- store valid rows (each token owned by exactly one expert) ----
#pragma unroll
    for (int rp = 0; rp < 4; rp++) {
        int row = w * 8 + rp * 2;
        float2 u0 = unpack2(acc[rp][0]), u1 = unpack2(acc[rp][1]);
        float2 u2 = unpack2(acc[rp][2]), u3 = unpack2(acc[rp][3]);
        if (i0 + row < cnte) {
            float* dst = out + ((size_t)b * NP + Sm.idxs[row]) * NDM + lane * 4;
            *reinterpret_cast<float4*>(dst) = make_float4(u0.x, u1.x, u2.x, u3.x);
        }
        if (i0 + row + 1 < cnte) {
            float* dst = out + ((size_t)b * NP + Sm.idxs[row + 1]) * NDM + lane * 4;
            *reinterpret_cast<float4*>(dst) = make_float4(u0.y, u1.y, u2.y, u3.y);
        }
    }
}

// ---------------- launch ----------------
extern "C" void kernel_launch(void* const* d_in, const int* in_sizes, int n_in,
                              void* d_out, int out_size)
{
    const float* tokens  = (const float*)d_in[0];
    const float* fingerp = (const float*)d_in[1];
    const float* alpha   = (const float*)d_in[2];
    const float* gw1     = (const float*)d_in[3];
    const float* gb1     = (const float*)d_in[4];
    const float* gw2     = (const float*)d_in[5];
    const float* gb2     = (const float*)d_in[6];
    const float* q_w     = (const float*)d_in[7];
    const float* k_w     = (const float*)d_in[8];
    const float* v_w     = (const float*)d_in[9];
    const float* penta   = (const float*)d_in[10];
    const float* fusion  = (const float*)d_in[11];
    const float* temp    = (const float*)d_in[12];
    float* out = (float*)d_out;

    cudaFuncSetAttribute(k_featproc, cudaFuncAttributeMaxDynamicSharedMemorySize, (int)sizeof(Smem2));
    cudaFuncSetAttribute(k_attn,     cudaFuncAttributeMaxDynamicSharedMemorySize, (int)sizeof(Smem3));

    k_setup<<<NE, 256>>>(alpha, penta, fusion, q_w, k_w, temp);
    k_dispatch<<<1, 512>>>(fingerp);
    int n4 = out_size / 4;
    k_zero<<<(n4 + 255) / 256, 256>>>(out, n4);
    k_featproc<<<dim3(NE, NB, 2), 256, sizeof(Smem2)>>>(tokens, gw1, gb1, gw2, gb2, v_w);
    k_attn<<<dim3(NE, NB, 4), 256, sizeof(Smem3)>>>(out);
}